// round 4
// baseline (speedup 1.0000x reference)
#include <cuda_runtime.h>
#include <cstdint>

#ifndef THRESH
#define THRESH 0.7f
#endif

// 2 slots per thread: widens score/keep stores to STG.64 while keeping
// register pressure and occupancy near the 1-slot kernel (R2's 4x variant
// dropped occupancy 79->52% and regressed).
// Output layout: [rects B*N*4][scores B*N][keep B*N]
__global__ void __launch_bounds__(256) rnet_post_kernel2(
    const float4* __restrict__ cls2,    // [total/2] : 2 slots per float4
    const float4* __restrict__ reg,     // [total]
    const float4* __restrict__ rects,   // [total]
    const int*    __restrict__ hptr,
    const int*    __restrict__ wptr,
    float4* __restrict__ out_rects,     // [total]
    float2* __restrict__ out_scores2,   // [total/2]
    float2* __restrict__ out_keep2,     // [total/2]
    int npairs)                         // total/2
{
    const float fh = (float)(*hptr);
    const float fw = (float)(*wptr);

    int i = blockIdx.x * blockDim.x + threadIdx.x;
    if (i >= npairs) return;

    const float4 c  = cls2[i];            // (p0a,p1a,p0b,p1b)
    const float4 r0 = rects[2 * i];
    const float4 r1 = rects[2 * i + 1];
    const float4 d0 = reg[2 * i];
    const float4 d1 = reg[2 * i + 1];

    const float k0 = (c.y > THRESH) ? 1.0f : 0.0f;
    const float k1 = (c.w > THRESH) ? 1.0f : 0.0f;

    const float w0 = r0.z - r0.x, h0 = r0.w - r0.y;
    const float w1 = r1.z - r1.x, h1 = r1.w - r1.y;

    float a_x1 = fminf(fmaxf(fmaf(d0.x, w0, r0.x), 0.0f), fw);
    float a_y1 = fminf(fmaxf(fmaf(d0.y, h0, r0.y), 0.0f), fh);
    float a_x2 = fminf(fmaxf(fmaf(d0.z, w0, r0.z), 0.0f), fw);
    float a_y2 = fminf(fmaxf(fmaf(d0.w, h0, r0.w), 0.0f), fh);

    float b_x1 = fminf(fmaxf(fmaf(d1.x, w1, r1.x), 0.0f), fw);
    float b_y1 = fminf(fmaxf(fmaf(d1.y, h1, r1.y), 0.0f), fh);
    float b_x2 = fminf(fmaxf(fmaf(d1.z, w1, r1.z), 0.0f), fw);
    float b_y2 = fminf(fmaxf(fmaf(d1.w, h1, r1.w), 0.0f), fh);

    out_rects[2 * i]     = make_float4(a_x1 * k0, a_y1 * k0, a_x2 * k0, a_y2 * k0);
    out_rects[2 * i + 1] = make_float4(b_x1 * k1, b_y1 * k1, b_x2 * k1, b_y2 * k1);
    out_scores2[i] = make_float2(c.y * k0, c.w * k1);
    out_keep2[i]   = make_float2(k0, k1);
}

// Tail for odd totals (not expected for B*N = 4M, but safe).
__global__ void rnet_post_tail(
    const float2* __restrict__ cls,
    const float4* __restrict__ reg,
    const float4* __restrict__ rects,
    const int* __restrict__ hptr, const int* __restrict__ wptr,
    float4* __restrict__ out_rects, float* __restrict__ out_scores,
    float* __restrict__ out_keep, int start, int total)
{
    int i = start + blockIdx.x * blockDim.x + threadIdx.x;
    if (i >= total) return;
    const float fh = (float)(*hptr);
    const float fw = (float)(*wptr);
    const float2 c = cls[i];
    const float4 r = rects[i];
    const float4 d = reg[i];
    const float keep = (c.y > THRESH) ? 1.0f : 0.0f;
    const float w = r.z - r.x, h = r.w - r.y;
    float nx1 = fminf(fmaxf(fmaf(d.x, w, r.x), 0.0f), fw);
    float ny1 = fminf(fmaxf(fmaf(d.y, h, r.y), 0.0f), fh);
    float nx2 = fminf(fmaxf(fmaf(d.z, w, r.z), 0.0f), fw);
    float ny2 = fminf(fmaxf(fmaf(d.w, h, r.w), 0.0f), fh);
    out_rects[i]  = make_float4(nx1 * keep, ny1 * keep, nx2 * keep, ny2 * keep);
    out_scores[i] = c.y * keep;
    out_keep[i]   = keep;
}

extern "C" void kernel_launch(void* const* d_in, const int* in_sizes, int n_in,
                              void* d_out, int out_size)
{
    const float* cls    = (const float*)d_in[0];  // classifier [B,N,2]
    const float4* reg   = (const float4*)d_in[1];
    const float4* rects = (const float4*)d_in[2];
    const int*    hptr  = (const int*)d_in[3];
    const int*    wptr  = (const int*)d_in[4];

    const int total  = in_sizes[0] / 2;  // B*N
    const int npairs = total / 2;
    const int tail_start = npairs * 2;

    float* out        = (float*)d_out;
    float4* out_rects = (float4*)out;
    float* out_scores = out + (size_t)total * 4;
    float* out_keep   = out + (size_t)total * 5;

    const int threads = 256;
    if (npairs > 0) {
        const int blocks = (npairs + threads - 1) / threads;
        rnet_post_kernel2<<<blocks, threads>>>(
            (const float4*)cls, reg, rects, hptr, wptr,
            out_rects, (float2*)out_scores, (float2*)out_keep, npairs);
    }
    if (tail_start < total) {
        const int nt = total - tail_start;
        rnet_post_tail<<<(nt + threads - 1) / threads, threads>>>(
            (const float2*)cls, reg, rects, hptr, wptr,
            out_rects, out_scores, out_keep, tail_start, total);
    }
}

// round 5
// speedup vs baseline: 1.0118x; 1.0118x over previous
#include <cuda_runtime.h>
#include <cstdint>

#ifndef THRESH
#define THRESH 0.7f
#endif

// FINAL (R1 config). HBM-bound elementwise postprocess.
// Measured plateau: 6.3 TB/s (80% of spec) across 4 structural variants
// (1/2/4 slots per thread, streaming cache hints) — this is the mixed
// read/write HBM ceiling for the 40B-read/24B-write per-slot 6-stream
// pattern. 1 thread/slot maximizes warp-level latency hiding (occ 79%,
// 28 regs) and is the simplest kernel on the plateau.
// Output layout: [rects B*N*4][scores B*N][keep B*N]
__global__ void __launch_bounds__(256) rnet_post_kernel(
    const float2* __restrict__ cls,    // [total] of (p0, p1)
    const float4* __restrict__ reg,    // [total] of (dx1,dy1,dx2,dy2)
    const float4* __restrict__ rects,  // [total] of (x1,y1,x2,y2)
    const int*    __restrict__ hptr,   // scalar H
    const int*    __restrict__ wptr,   // scalar W
    float4* __restrict__ out_rects,    // [total]
    float*  __restrict__ out_scores,   // [total]
    float*  __restrict__ out_keep,     // [total]
    int total)
{
    const float fh = (float)(*hptr);
    const float fw = (float)(*wptr);

    int i = blockIdx.x * blockDim.x + threadIdx.x;
    if (i >= total) return;

    const float2 c = cls[i];
    const float4 r = rects[i];
    const float4 d = reg[i];

    const float score = c.y;
    const float keep  = (score > THRESH) ? 1.0f : 0.0f;

    const float w = r.z - r.x;
    const float h = r.w - r.y;

    float nx1 = fminf(fmaxf(fmaf(d.x, w, r.x), 0.0f), fw);
    float ny1 = fminf(fmaxf(fmaf(d.y, h, r.y), 0.0f), fh);
    float nx2 = fminf(fmaxf(fmaf(d.z, w, r.z), 0.0f), fw);
    float ny2 = fminf(fmaxf(fmaf(d.w, h, r.w), 0.0f), fh);

    out_rects[i]  = make_float4(nx1 * keep, ny1 * keep, nx2 * keep, ny2 * keep);
    out_scores[i] = score * keep;
    out_keep[i]   = keep;
}

extern "C" void kernel_launch(void* const* d_in, const int* in_sizes, int n_in,
                              void* d_out, int out_size)
{
    const float2* cls   = (const float2*)d_in[0];  // classifier [B,N,2]
    const float4* reg   = (const float4*)d_in[1];  // bbox_regress [B,N,4]
    const float4* rects = (const float4*)d_in[2];  // input_rects [B,N,4]
    const int*    hptr  = (const int*)d_in[3];     // input_height scalar
    const int*    wptr  = (const int*)d_in[4];     // input_width scalar

    const int total = in_sizes[0] / 2;             // B*N

    float* out        = (float*)d_out;
    float4* out_rects = (float4*)out;              // total * 4 floats
    float* out_scores = out + (size_t)total * 4;   // total floats
    float* out_keep   = out + (size_t)total * 5;   // total floats

    const int threads = 256;
    const int blocks  = (total + threads - 1) / threads;
    rnet_post_kernel<<<blocks, threads>>>(cls, reg, rects, hptr, wptr,
                                          out_rects, out_scores, out_keep, total);
}